// round 5
// baseline (speedup 1.0000x reference)
#include <cuda_runtime.h>
#include <cstdint>
#include <cstddef>

#define Bdim 8
#define Ndim 4096
#define Cdim 512
#define Hdim 4
#define Mdim (Bdim*Ndim)   /* 32768 */
#define Kdim (2*Cdim)      /* 1024  */

// scratch: z in k-major [K][M], W transposed [K][N]
__device__ float g_zt[(size_t)Kdim * Mdim];
__device__ float g_wt[(size_t)Kdim * Cdim];

__device__ __forceinline__ float ex2f(float x) {
    float y;
    asm("ex2.approx.ftz.f32 %0, %1;" : "=f"(y) : "f"(x));
    return y;
}

// ---------------------------------------------------------------------------
// W transpose: g_wt[k][n] = proj_w[n][k]
// ---------------------------------------------------------------------------
__global__ void wt_kernel(const float* __restrict__ W)
{
    __shared__ float t[32][33];
    int k0 = blockIdx.x * 32;   // 1024/32 = 32
    int n0 = blockIdx.y * 32;   // 512/32  = 16
    int tx = threadIdx.x, ty = threadIdx.y;  // 32x8
#pragma unroll
    for (int j = 0; j < 32; j += 8)
        t[ty + j][tx] = W[(size_t)(n0 + ty + j) * Kdim + k0 + tx];
    __syncthreads();
#pragma unroll
    for (int j = 0; j < 32; j += 8)
        g_wt[(size_t)(k0 + ty + j) * Cdim + n0 + tx] = t[tx][ty + j];
}

// ---------------------------------------------------------------------------
// Clipped EMA scan (fwd + bwd), writes y into g_zt[(dir*C + c)][b*N + n]
// grid.x = 2 * B * (C/8) = 1024 blocks, 256 threads (8 warps = 8 channels)
// ---------------------------------------------------------------------------
__global__ __launch_bounds__(256) void scan_kernel(
    const float* __restrict__ x,
    const float* __restrict__ al, const float* __restrict__ dl,
    const float* __restrict__ bl, const float* __restrict__ eta)
{
    const int CG = Cdim / 8;           // 64 channel groups
    int blk = blockIdx.x;
    int cg  = blk % CG;
    int b   = (blk / CG) % Bdim;
    int dir = blk / (CG * Bdim);       // 0 fwd, 1 bwd
    int c0  = cg * 8;

    __shared__ float xs[32][9];
    __shared__ float sA[8][4], sLr[8][4], sEt[8][4];

    int tid = threadIdx.x;
    if (tid < 32) {
        int cc = tid >> 2, h = tid & 3;
        int idx = (c0 + cc) * Hdim + h;
        float a  = 1.0f / (1.0f + expf(-al[idx]));
        float dd = 1.0f / (1.0f + expf(-dl[idx]));
        float be = 1.0f / (1.0f + expf(-bl[idx]));
        float r  = 1.0f - a * dd;
        r = fminf(fmaxf(r, 1e-4f), 1.0f - 1e-4f);
        sA[cc][h]  = a * be;
        sLr[cc][h] = log2f(r);          // accurate log2 (avoid lg2.approx near r~1)
        sEt[cc][h] = eta[idx];
    }
    __syncthreads();

    int w = tid >> 5, lane = tid & 31;
    float Ah[4], Lr[4], Et[4], carry[4];
#pragma unroll
    for (int h = 0; h < 4; h++) {
        Ah[h] = sA[w][h]; Lr[h] = sLr[w][h]; Et[h] = sEt[w][h]; carry[h] = 0.0f;
    }

    const float CLP = 86.56170245333781f;   // 60 * log2(e)
    int ltt = tid >> 3, lcc = tid & 7;

    for (int t0 = 0; t0 < Ndim; t0 += 32) {
        // cooperative coalesced load of x tile [32 t][8 c]
        int s_ld = t0 + ltt;
        int n_ld = dir ? (Ndim - 1 - s_ld) : s_ld;
        xs[ltt][lcc] = x[((size_t)b * Ndim + n_ld) * Cdim + c0 + lcc];
        __syncthreads();

        float xv = xs[lane][w];
        float sf = (float)(t0 + lane);
        float y  = 0.0f;
#pragma unroll
        for (int h = 0; h < 4; h++) {
            float e = Lr[h] * sf;
            e = fmaxf(e, -CLP);          // lr<0, s>=0 -> e<=0; lower clip only
            float p = ex2f(e);
            float q = ex2f(-e);
            float z = Ah[h] * xv * q;
            float ss = z;
#pragma unroll
            for (int o = 1; o < 32; o <<= 1) {
                float v = __shfl_up_sync(0xffffffffu, ss, o);
                if (lane >= o) ss += v;
            }
            float St = ss + carry[h];
            y = fmaf(Et[h], St * p, y);
            carry[h] = __shfl_sync(0xffffffffu, St, 31);
        }
        // direct coalesced store: warp w = channel c0+w, lanes run over time
        int n_st = dir ? (Ndim - 1 - (t0 + lane)) : (t0 + lane);
        g_zt[(size_t)(dir * Cdim + c0 + w) * Mdim + (size_t)b * Ndim + n_st] = y;
        __syncthreads();
    }
}

// ---------------------------------------------------------------------------
// TN SGEMM with packed f32x2 FMA: out[m][n] = bias[n] + sum_k zt[k][m]*wt[k][n]
// 128x128x16 tiles, 256 threads, 8x8 microtile, double-buffered smem
// ---------------------------------------------------------------------------
__global__ __launch_bounds__(256) void gemm_kernel(const float* __restrict__ bias,
                                                   float* __restrict__ out)
{
    __shared__ float As[2][16][128];
    __shared__ float Bs[2][16][128];

    int tid = threadIdx.x;
    int m0 = blockIdx.x * 128;   // 256
    int n0 = blockIdx.y * 128;   // 4
    int tx = tid & 15, ty = tid >> 4;
    int lk = tid >> 5, lq = tid & 31;

    const float* Za = g_zt + (size_t)lk * Mdim + m0 + lq * 4;
    const float* Wa = g_wt + (size_t)lk * Cdim + n0 + lq * 4;

    unsigned long long acc[8][4];
#pragma unroll
    for (int i = 0; i < 8; i++)
#pragma unroll
        for (int j = 0; j < 4; j++) acc[i][j] = 0ull;

    // prologue: tile 0 -> buf 0
    {
        float4 a0 = *(const float4*)(Za);
        float4 a1 = *(const float4*)(Za + (size_t)8 * Mdim);
        float4 b0 = *(const float4*)(Wa);
        float4 b1 = *(const float4*)(Wa + (size_t)8 * Cdim);
        *(float4*)&As[0][lk    ][lq * 4] = a0;
        *(float4*)&As[0][lk + 8][lq * 4] = a1;
        *(float4*)&Bs[0][lk    ][lq * 4] = b0;
        *(float4*)&Bs[0][lk + 8][lq * 4] = b1;
    }
    __syncthreads();

    int cur = 0;
    for (int kt = 0; kt < 64; kt++) {
        float4 na0, na1, nb0, nb1;
        if (kt < 63) {
            const float* Zn = Za + (size_t)(kt + 1) * 16 * Mdim;
            const float* Wn = Wa + (size_t)(kt + 1) * 16 * Cdim;
            na0 = *(const float4*)(Zn);
            na1 = *(const float4*)(Zn + (size_t)8 * Mdim);
            nb0 = *(const float4*)(Wn);
            nb1 = *(const float4*)(Wn + (size_t)8 * Cdim);
        }
#pragma unroll
        for (int k = 0; k < 16; k++) {
            float a[8], bv[8];
            *(float4*)(a)      = *(const float4*)&As[cur][k][ty * 8];
            *(float4*)(a + 4)  = *(const float4*)&As[cur][k][ty * 8 + 4];
            *(float4*)(bv)     = *(const float4*)&Bs[cur][k][tx * 8];
            *(float4*)(bv + 4) = *(const float4*)&Bs[cur][k][tx * 8 + 4];
            unsigned long long b2[4];
#pragma unroll
            for (int j = 0; j < 4; j++)
                asm("mov.b64 %0, {%1, %2};" : "=l"(b2[j]) : "f"(bv[2 * j]), "f"(bv[2 * j + 1]));
#pragma unroll
            for (int i = 0; i < 8; i++) {
                unsigned long long aa;
                asm("mov.b64 %0, {%1, %2};" : "=l"(aa) : "f"(a[i]), "f"(a[i]));
#pragma unroll
                for (int j = 0; j < 4; j++)
                    asm("fma.rn.f32x2 %0, %1, %2, %0;" : "+l"(acc[i][j]) : "l"(aa), "l"(b2[j]));
            }
        }
        if (kt < 63) {
            *(float4*)&As[cur ^ 1][lk    ][lq * 4] = na0;
            *(float4*)&As[cur ^ 1][lk + 8][lq * 4] = na1;
            *(float4*)&Bs[cur ^ 1][lk    ][lq * 4] = nb0;
            *(float4*)&Bs[cur ^ 1][lk + 8][lq * 4] = nb1;
            __syncthreads();
            cur ^= 1;
        }
    }

    // epilogue: add bias, store (out is [B,N,C] = [m][n] row-major)
    const float* bp = bias + n0 + tx * 8;
    float bl_[8];
    *(float4*)(bl_)     = *(const float4*)(bp);
    *(float4*)(bl_ + 4) = *(const float4*)(bp + 4);
#pragma unroll
    for (int i = 0; i < 8; i++) {
        float* op = out + (size_t)(m0 + ty * 8 + i) * Cdim + n0 + tx * 8;
        float r[8];
#pragma unroll
        for (int j = 0; j < 4; j++) {
            float lo, hi;
            asm("mov.b64 {%0, %1}, %2;" : "=f"(lo), "=f"(hi) : "l"(acc[i][j]));
            r[2 * j]     = lo + bl_[2 * j];
            r[2 * j + 1] = hi + bl_[2 * j + 1];
        }
        *(float4*)(op)     = *(const float4*)(r);
        *(float4*)(op + 4) = *(const float4*)(r + 4);
    }
}

// ---------------------------------------------------------------------------
extern "C" void kernel_launch(void* const* d_in, const int* in_sizes, int n_in,
                              void* d_out, int out_size)
{
    const float* x  = (const float*)d_in[0];
    const float* al = (const float*)d_in[1];
    const float* dl = (const float*)d_in[2];
    const float* bl = (const float*)d_in[3];
    const float* et = (const float*)d_in[4];
    const float* pw = (const float*)d_in[5];
    const float* pb = (const float*)d_in[6];
    float* out = (float*)d_out;

    wt_kernel<<<dim3(Kdim / 32, Cdim / 32), dim3(32, 8)>>>(pw);
    scan_kernel<<<dim3(2 * Bdim * (Cdim / 8)), 256>>>(x, al, dl, bl, et);
    gemm_kernel<<<dim3(Mdim / 128, Cdim / 128), 256>>>(pb, out);
}

// round 8
// speedup vs baseline: 1.5537x; 1.5537x over previous
#include <cuda_runtime.h>
#include <cuda_bf16.h>
#include <cstdint>
#include <cstddef>

#define Bdim 8
#define Ndim 4096
#define Cdim 512
#define Hdim 4
#define Mdim (Bdim*Ndim)   /* 32768 */
#define Kdim (2*Cdim)      /* 1024  */

// A (scan output) [M][K] bf16 hi/lo; B (proj_w) [N][K] bf16 hi/lo
__device__ __align__(128) __nv_bfloat16 g_ah[(size_t)Mdim * Kdim];
__device__ __align__(128) __nv_bfloat16 g_al[(size_t)Mdim * Kdim];
__device__ __align__(128) __nv_bfloat16 g_bh[(size_t)Cdim * Kdim];
__device__ __align__(128) __nv_bfloat16 g_bl[(size_t)Cdim * Kdim];

__device__ __forceinline__ float ex2f(float x) {
    float y;
    asm("ex2.approx.ftz.f32 %0, %1;" : "=f"(y) : "f"(x));
    return y;
}

__device__ __forceinline__ uint32_t smem_u32(const void* p) {
    uint32_t a;
    asm("{ .reg .u64 t; cvta.to.shared.u64 t, %1; cvt.u32.u64 %0, t; }" : "=r"(a) : "l"(p));
    return a;
}

__device__ __forceinline__ void cp16(uint32_t dst, const void* src) {
    asm volatile("cp.async.cg.shared.global [%0], [%1], 16;" :: "r"(dst), "l"(src));
}

__device__ __forceinline__ void ldsm4(uint32_t* r, uint32_t a) {
    asm volatile("ldmatrix.sync.aligned.m8n8.x4.shared.b16 {%0,%1,%2,%3}, [%4];"
        : "=r"(r[0]), "=r"(r[1]), "=r"(r[2]), "=r"(r[3]) : "r"(a));
}

__device__ __forceinline__ void mma16816(float* d, const uint32_t* a, const uint32_t* b) {
    asm volatile("mma.sync.aligned.m16n8k16.row.col.f32.bf16.bf16.f32 "
        "{%0,%1,%2,%3}, {%4,%5,%6,%7}, {%8,%9}, {%0,%1,%2,%3};"
        : "+f"(d[0]), "+f"(d[1]), "+f"(d[2]), "+f"(d[3])
        : "r"(a[0]), "r"(a[1]), "r"(a[2]), "r"(a[3]), "r"(b[0]), "r"(b[1]));
}

// ---------------------------------------------------------------------------
// W convert: g_bh/g_bl[n][k] = hi/lo bf16 of proj_w[n][k]
// ---------------------------------------------------------------------------
__global__ void wconv_kernel(const float* __restrict__ W)
{
    int i = blockIdx.x * 256 + threadIdx.x;   // 2048 x 256
    float v = W[i];
    __nv_bfloat16 h = __float2bfloat16(v);
    g_bh[i] = h;
    g_bl[i] = __float2bfloat16(v - __bfloat162float(h));
}

// ---------------------------------------------------------------------------
// Clipped EMA scan (fwd + bwd) -> bf16 hi/lo in [M][K]
// grid = 2*B*(C/8) = 1024 blocks, 256 threads (8 warps = 8 channels)
// ---------------------------------------------------------------------------
__global__ __launch_bounds__(256) void scan_kernel(
    const float* __restrict__ x,
    const float* __restrict__ al, const float* __restrict__ dl,
    const float* __restrict__ bl, const float* __restrict__ eta)
{
    const int CG = Cdim / 8;
    int blk = blockIdx.x;
    int cg  = blk % CG;
    int b   = (blk / CG) % Bdim;
    int dir = blk / (CG * Bdim);
    int c0  = cg * 8;

    __shared__ float xs[32][9];
    __shared__ float ys[32][9];
    __shared__ float sA[8][4], sLr[8][4], sEt[8][4];

    int tid = threadIdx.x;
    if (tid < 32) {
        int cc = tid >> 2, h = tid & 3;
        int idx = (c0 + cc) * Hdim + h;
        float a  = 1.0f / (1.0f + expf(-al[idx]));
        float dd = 1.0f / (1.0f + expf(-dl[idx]));
        float be = 1.0f / (1.0f + expf(-bl[idx]));
        float r  = 1.0f - a * dd;
        r = fminf(fmaxf(r, 1e-4f), 1.0f - 1e-4f);
        sA[cc][h]  = a * be;
        sLr[cc][h] = log2f(r);
        sEt[cc][h] = eta[idx];
    }
    __syncthreads();

    int w = tid >> 5, lane = tid & 31;
    float Ah[4], Lr[4], Et[4], carry[4];
#pragma unroll
    for (int h = 0; h < 4; h++) {
        Ah[h] = sA[w][h]; Lr[h] = sLr[w][h]; Et[h] = sEt[w][h]; carry[h] = 0.0f;
    }

    const float CLP = 86.56170245333781f;   // 60 * log2(e)
    int ltt = tid >> 3, lcc = tid & 7;

    for (int t0 = 0; t0 < Ndim; t0 += 32) {
        int s_ld = t0 + ltt;
        int n_ld = dir ? (Ndim - 1 - s_ld) : s_ld;
        xs[ltt][lcc] = x[((size_t)b * Ndim + n_ld) * Cdim + c0 + lcc];
        __syncthreads();

        float xv = xs[lane][w];
        float sf = (float)(t0 + lane);
        float y  = 0.0f;
#pragma unroll
        for (int h = 0; h < 4; h++) {
            float e = Lr[h] * sf;
            e = fmaxf(e, -CLP);
            float p = ex2f(e);
            float q = ex2f(-e);
            float z = Ah[h] * xv * q;
            float ss = z;
#pragma unroll
            for (int o = 1; o < 32; o <<= 1) {
                float v = __shfl_up_sync(0xffffffffu, ss, o);
                if (lane >= o) ss += v;
            }
            float St = ss + carry[h];
            y = fmaf(Et[h], St * p, y);
            carry[h] = __shfl_sync(0xffffffffu, St, 31);
        }
        ys[lane][w] = y;
        __syncthreads();

        if (tid < 64) {
            int half = tid >> 5;       // 0 = hi, 1 = lo
            int tt = tid & 31;
            int n_st = dir ? (Ndim - 1 - (t0 + tt)) : (t0 + tt);
            size_t m = (size_t)b * Ndim + n_st;
            uint4 u;
            unsigned* up = (unsigned*)&u;
#pragma unroll
            for (int j = 0; j < 4; j++) {
                float v0 = ys[tt][2 * j], v1 = ys[tt][2 * j + 1];
                __nv_bfloat162 pk;
                if (half == 0) {
                    pk = __floats2bfloat162_rn(v0, v1);
                } else {
                    __nv_bfloat16 h0 = __float2bfloat16(v0);
                    __nv_bfloat16 h1 = __float2bfloat16(v1);
                    pk = __floats2bfloat162_rn(v0 - __bfloat162float(h0),
                                               v1 - __bfloat162float(h1));
                }
                up[j] = *(unsigned*)&pk;
            }
            __nv_bfloat16* base = half ? g_al : g_ah;
            *(uint4*)(base + m * Kdim + dir * Cdim + c0) = u;
        }
    }
}

// ---------------------------------------------------------------------------
// HMMA (mma.sync bf16) split GEMM: out[m][n] = bias[n] + sum_k z[m][k]W[n][k]
// via AhBh + AhBl + AlBh. CTA tile 256x128, K-chunk 32, 3-stage cp.async,
// 512 threads (16 warps, warp tile 64x32). grid (4 n-tiles, 128 m-tiles).
// ---------------------------------------------------------------------------
#define ROWB 80                              /* 64 data + 16 pad: conflict-free ldmatrix */
#define AH_OFF 0
#define AL_OFF (256*ROWB)                    /* 20480 */
#define BH_OFF (2*256*ROWB)                  /* 40960 */
#define BL_OFF (BH_OFF + 128*ROWB)           /* 51200 */
#define STAGE_BYTES (BL_OFF + 128*ROWB)      /* 61440 */
#define BIAS_OFF (3*STAGE_BYTES)             /* 184320 */
#define GEMM_SMEM (BIAS_OFF + 512)

__global__ void __launch_bounds__(512, 1) gemm_hmma(const float* __restrict__ bias,
                                                    float* __restrict__ out)
{
    extern __shared__ char smem[];
    const uint32_t sb = smem_u32(smem);
    int tid  = threadIdx.x;
    int wid  = tid >> 5, lane = tid & 31;
    int n0   = blockIdx.x * 128;
    int m0   = blockIdx.y * 256;
    int wm   = (wid & 3) * 64;
    int wn   = (wid >> 2) * 32;

    if (tid < 128) ((float*)(smem + BIAS_OFF))[tid] = bias[n0 + tid];

    auto load_chunk = [&](int kt, int buf) {
        uint32_t st = sb + (uint32_t)buf * STAGE_BYTES;
        int koff = kt * 32;
#pragma unroll
        for (int i = 0; i < 2; i++) {
            int q = tid + i * 512;
            int r = q >> 2, c = q & 3;
            cp16(st + AH_OFF + r * ROWB + c * 16,
                 g_ah + (size_t)(m0 + r) * Kdim + koff + c * 8);
            cp16(st + AL_OFF + r * ROWB + c * 16,
                 g_al + (size_t)(m0 + r) * Kdim + koff + c * 8);
        }
        {
            int r = tid >> 2, c = tid & 3;
            cp16(st + BH_OFF + r * ROWB + c * 16,
                 g_bh + (size_t)(n0 + r) * Kdim + koff + c * 8);
            cp16(st + BL_OFF + r * ROWB + c * 16,
                 g_bl + (size_t)(n0 + r) * Kdim + koff + c * 8);
        }
        asm volatile("cp.async.commit_group;" ::: "memory");
    };

    // per-thread ldmatrix address offsets (x4 lane mapping)
    const uint32_t a_off =
        (uint32_t)((wm + (lane & 7) + ((lane >> 3) & 1) * 8) * ROWB + ((lane >> 4) & 1) * 16);
    const uint32_t b_off =
        (uint32_t)((wn + (lane & 7) + ((lane >> 4) & 1) * 8) * ROWB + ((lane >> 3) & 1) * 16);

    float acc[4][4][4];
#pragma unroll
    for (int mi = 0; mi < 4; mi++)
#pragma unroll
        for (int ni = 0; ni < 4; ni++)
#pragma unroll
            for (int j = 0; j < 4; j++) acc[mi][ni][j] = 0.0f;

    load_chunk(0, 0);
    load_chunk(1, 1);

    for (int kt = 0; kt < 32; kt++) {
        if (kt + 2 < 32) load_chunk(kt + 2, (kt + 2) % 3);
        if (kt < 30)       asm volatile("cp.async.wait_group 2;" ::: "memory");
        else if (kt == 30) asm volatile("cp.async.wait_group 1;" ::: "memory");
        else               asm volatile("cp.async.wait_group 0;" ::: "memory");
        __syncthreads();

        uint32_t st = sb + (uint32_t)(kt % 3) * STAGE_BYTES;
#pragma unroll
        for (int s = 0; s < 2; s++) {
            uint32_t af[4][4], bh[4][2], blo[4][2];
#pragma unroll
            for (int mi = 0; mi < 4; mi++)
                ldsm4(af[mi], st + AH_OFF + a_off + mi * 16 * ROWB + s * 32);
#pragma unroll
            for (int j = 0; j < 2; j++) {
                uint32_t t4[4];
                ldsm4(t4, st + BH_OFF + b_off + j * 16 * ROWB + s * 32);
                bh[2 * j][0] = t4[0]; bh[2 * j][1] = t4[1];
                bh[2 * j + 1][0] = t4[2]; bh[2 * j + 1][1] = t4[3];
                ldsm4(t4, st + BL_OFF + b_off + j * 16 * ROWB + s * 32);
                blo[2 * j][0] = t4[0]; blo[2 * j][1] = t4[1];
                blo[2 * j + 1][0] = t4[2]; blo[2 * j + 1][1] = t4[3];
            }
            // hh + hl terms with Ah resident
#pragma unroll
            for (int mi = 0; mi < 4; mi++)
#pragma unroll
                for (int ni = 0; ni < 4; ni++) {
                    mma16816(acc[mi][ni], af[mi], bh[ni]);
                    mma16816(acc[mi][ni], af[mi], blo[ni]);
                }
            // lh term: reload A-low over the same fragment registers
#pragma unroll
            for (int mi = 0; mi < 4; mi++)
                ldsm4(af[mi], st + AL_OFF + a_off + mi * 16 * ROWB + s * 32);
#pragma unroll
            for (int mi = 0; mi < 4; mi++)
#pragma unroll
                for (int ni = 0; ni < 4; ni++)
                    mma16816(acc[mi][ni], af[mi], bh[ni]);
        }
        __syncthreads();
    }

    // epilogue: regs -> padded smem staging -> +bias -> coalesced float4 STG
    float* stg = (float*)smem;               // [256][132]
#pragma unroll
    for (int mi = 0; mi < 4; mi++)
#pragma unroll
        for (int ni = 0; ni < 4; ni++) {
            int r0 = wm + mi * 16 + (lane >> 2);
            int cc = wn + ni * 8 + (lane & 3) * 2;
            *(float2*)&stg[r0 * 132 + cc]       = make_float2(acc[mi][ni][0], acc[mi][ni][1]);
            *(float2*)&stg[(r0 + 8) * 132 + cc] = make_float2(acc[mi][ni][2], acc[mi][ni][3]);
        }
    __syncthreads();
    const float* bsm = (const float*)(smem + BIAS_OFF);
#pragma unroll
    for (int i = 0; i < 16; i++) {
        int f = tid + i * 512;
        int r = f >> 5, c4 = (f & 31) * 4;
        float4 v = *(const float4*)&stg[r * 132 + c4];
        v.x += bsm[c4]; v.y += bsm[c4 + 1]; v.z += bsm[c4 + 2]; v.w += bsm[c4 + 3];
        *(float4*)&out[(size_t)(m0 + r) * Cdim + n0 + c4] = v;
    }
}

// ---------------------------------------------------------------------------
extern "C" void kernel_launch(void* const* d_in, const int* in_sizes, int n_in,
                              void* d_out, int out_size)
{
    const float* x  = (const float*)d_in[0];
    const float* al = (const float*)d_in[1];
    const float* dl = (const float*)d_in[2];
    const float* bl = (const float*)d_in[3];
    const float* et = (const float*)d_in[4];
    const float* pw = (const float*)d_in[5];
    const float* pb = (const float*)d_in[6];
    float* out = (float*)d_out;

    cudaFuncSetAttribute(gemm_hmma, cudaFuncAttributeMaxDynamicSharedMemorySize, GEMM_SMEM);

    wconv_kernel<<<2048, 256>>>(pw);
    scan_kernel<<<dim3(2 * Bdim * (Cdim / 8)), 256>>>(x, al, dl, bl, et);
    gemm_hmma<<<dim3(Cdim / 128, Mdim / 256), 512, GEMM_SMEM>>>(pb, out);
}

// round 11
// speedup vs baseline: 2.3284x; 1.4987x over previous
// v10-resubmit (R9 theory, unmeasured due to broker outage)
#include <cuda_runtime.h>
#include <cuda_bf16.h>
#include <cstdint>
#include <cstddef>

#define Bdim 8
#define Ndim 4096
#define Cdim 512
#define Hdim 4
#define Mdim (Bdim*Ndim)   /* 32768 */
#define Kdim (2*Cdim)      /* 1024  */

// A (scan output) [M][K] bf16 hi/lo; B (proj_w) [N][K] bf16 hi/lo
__device__ __align__(128) __nv_bfloat16 g_ah[(size_t)Mdim * Kdim];
__device__ __align__(128) __nv_bfloat16 g_al[(size_t)Mdim * Kdim];
__device__ __align__(128) __nv_bfloat16 g_bh[(size_t)Cdim * Kdim];
__device__ __align__(128) __nv_bfloat16 g_bl[(size_t)Cdim * Kdim];

__device__ __forceinline__ float ex2f(float x) {
    float y;
    asm("ex2.approx.ftz.f32 %0, %1;" : "=f"(y) : "f"(x));
    return y;
}

__device__ __forceinline__ uint32_t smem_u32(const void* p) {
    uint32_t a;
    asm("{ .reg .u64 t; cvta.to.shared.u64 t, %1; cvt.u32.u64 %0, t; }" : "=r"(a) : "l"(p));
    return a;
}

__device__ __forceinline__ void cp16(uint32_t dst, const void* src) {
    asm volatile("cp.async.cg.shared.global [%0], [%1], 16;" :: "r"(dst), "l"(src));
}

__device__ __forceinline__ void ldsm4(uint32_t* r, uint32_t a) {
    asm volatile("ldmatrix.sync.aligned.m8n8.x4.shared.b16 {%0,%1,%2,%3}, [%4];"
        : "=r"(r[0]), "=r"(r[1]), "=r"(r[2]), "=r"(r[3]) : "r"(a));
}

__device__ __forceinline__ void mma16816(float* d, const uint32_t* a, const uint32_t* b) {
    asm volatile("mma.sync.aligned.m16n8k16.row.col.f32.bf16.bf16.f32 "
        "{%0,%1,%2,%3}, {%4,%5,%6,%7}, {%8,%9}, {%0,%1,%2,%3};"
        : "+f"(d[0]), "+f"(d[1]), "+f"(d[2]), "+f"(d[3])
        : "r"(a[0]), "r"(a[1]), "r"(a[2]), "r"(a[3]), "r"(b[0]), "r"(b[1]));
}

// ---------------------------------------------------------------------------
// W convert: g_bh/g_bl[n][k] = hi/lo bf16 of proj_w[n][k]
// ---------------------------------------------------------------------------
__global__ void wconv_kernel(const float* __restrict__ W)
{
    int i = blockIdx.x * 256 + threadIdx.x;   // 2048 x 256
    float v = W[i];
    __nv_bfloat16 h = __float2bfloat16(v);
    g_bh[i] = h;
    g_bl[i] = __float2bfloat16(v - __bfloat162float(h));
}

// ---------------------------------------------------------------------------
// Clipped EMA scan (fwd + bwd) -> bf16 hi/lo in [M][K]
// grid = 2*B*(C/8) = 1024 blocks, 256 threads (8 warps = 8 channels)
// 128-timestep tiles: 4 elems/thread serial + one 5-step warp scan
// ---------------------------------------------------------------------------
#define XS_STRIDE 140   /* floats; 140*4 % 16 == 0, conflict-free stores */
#define YS_STRIDE 136   /* floats; 136*4 % 16 == 0 */

__global__ __launch_bounds__(256) void scan_kernel(
    const float* __restrict__ x,
    const float* __restrict__ al, const float* __restrict__ dl,
    const float* __restrict__ bl, const float* __restrict__ eta)
{
    const int CG = Cdim / 8;
    int blk = blockIdx.x;
    int cg  = blk % CG;
    int b   = (blk / CG) % Bdim;
    int dir = blk / (CG * Bdim);
    int c0  = cg * 8;

    __shared__ float xs2[8 * XS_STRIDE];   // [c][t]
    __shared__ float ys2[8 * YS_STRIDE];   // [c][t]
    __shared__ float sA[8][4], sLr[8][4], sEt[8][4];

    int tid = threadIdx.x;
    if (tid < 32) {
        int cc = tid >> 2, h = tid & 3;
        int idx = (c0 + cc) * Hdim + h;
        float a  = 1.0f / (1.0f + expf(-al[idx]));
        float dd = 1.0f / (1.0f + expf(-dl[idx]));
        float be = 1.0f / (1.0f + expf(-bl[idx]));
        float r  = 1.0f - a * dd;
        r = fminf(fmaxf(r, 1e-4f), 1.0f - 1e-4f);
        sA[cc][h]  = a * be;
        sLr[cc][h] = log2f(r);
        sEt[cc][h] = eta[idx];
    }
    __syncthreads();

    int w = tid >> 5, lane = tid & 31;
    float Ah[4], Lr[4], Et[4], carry[4];
#pragma unroll
    for (int h = 0; h < 4; h++) {
        Ah[h] = sA[w][h]; Lr[h] = sLr[w][h]; Et[h] = sEt[w][h]; carry[h] = 0.0f;
    }

    const float CLP = 86.56170245333781f;   // 60 * log2(e)
    int ldt = tid >> 1, ldh = tid & 1;      // loader: time, channel-half
    int wtt = tid & 127, wsel = tid >> 7;   // writer: time, hi/lo select

    for (int t0 = 0; t0 < Ndim; t0 += 128) {
        // load x tile [128 t][8 c] -> xs2 [c][t] transposed, conflict-free
        {
            int n_ld = dir ? (Ndim - 1 - (t0 + ldt)) : (t0 + ldt);
            float4 v = *(const float4*)&x[((size_t)b * Ndim + n_ld) * Cdim + c0 + ldh * 4];
            xs2[(ldh * 4 + 0) * XS_STRIDE + ldt] = v.x;
            xs2[(ldh * 4 + 1) * XS_STRIDE + ldt] = v.y;
            xs2[(ldh * 4 + 2) * XS_STRIDE + ldt] = v.z;
            xs2[(ldh * 4 + 3) * XS_STRIDE + ldt] = v.w;
        }
        __syncthreads();

        float4 xq = *(const float4*)&xs2[w * XS_STRIDE + lane * 4];
        float xv[4] = {xq.x, xq.y, xq.z, xq.w};
        float yv[4] = {0.0f, 0.0f, 0.0f, 0.0f};
        float s0 = (float)(t0 + lane * 4);

#pragma unroll
        for (int h = 0; h < 4; h++) {
            float p[4], z[4];
#pragma unroll
            for (int j = 0; j < 4; j++) {
                float e = Lr[h] * (s0 + (float)j);
                e = fmaxf(e, -CLP);
                p[j] = ex2f(e);
                z[j] = Ah[h] * xv[j] * ex2f(-e);
            }
            z[1] += z[0]; z[2] += z[1]; z[3] += z[2];   // local inclusive
            float tot = z[3];
            float ss = tot;
#pragma unroll
            for (int o = 1; o < 32; o <<= 1) {
                float v = __shfl_up_sync(0xffffffffu, ss, o);
                if (lane >= o) ss += v;
            }
            float blkTot = __shfl_sync(0xffffffffu, ss, 31);
            float pre = ss - tot + carry[h];             // exclusive prefix + carry
#pragma unroll
            for (int j = 0; j < 4; j++)
                yv[j] = fmaf(Et[h], (pre + z[j]) * p[j], yv[j]);
            carry[h] += blkTot;
        }

        // stage y: [c][t] float4 store, conflict-free
        *(float4*)&ys2[w * YS_STRIDE + lane * 4] = make_float4(yv[0], yv[1], yv[2], yv[3]);
        __syncthreads();

        // writers: 128 threads hi, 128 threads lo; each packs 8 channels
        {
            int n_st = dir ? (Ndim - 1 - (t0 + wtt)) : (t0 + wtt);
            size_t m = (size_t)b * Ndim + n_st;
            uint4 u;
            unsigned* up = (unsigned*)&u;
#pragma unroll
            for (int j = 0; j < 4; j++) {
                float v0 = ys2[(2 * j) * YS_STRIDE + wtt];
                float v1 = ys2[(2 * j + 1) * YS_STRIDE + wtt];
                __nv_bfloat162 pk;
                if (wsel == 0) {
                    pk = __floats2bfloat162_rn(v0, v1);
                } else {
                    __nv_bfloat16 h0 = __float2bfloat16(v0);
                    __nv_bfloat16 h1 = __float2bfloat16(v1);
                    pk = __floats2bfloat162_rn(v0 - __bfloat162float(h0),
                                               v1 - __bfloat162float(h1));
                }
                up[j] = *(unsigned*)&pk;
            }
            __nv_bfloat16* base = wsel ? g_al : g_ah;
            *(uint4*)(base + m * Kdim + dir * Cdim + c0) = u;
        }
        __syncthreads();
    }
}

// ---------------------------------------------------------------------------
// HMMA split GEMM: out[m][n] = bias[n] + sum_k z[m][k]W[n][k]
// AhBh + AhBl + AlBh. CTA tile 128x128, K-chunk 32, 2-stage cp.async,
// 256 threads (8 warps, warp tile 64x32), 2 CTAs/SM. grid (4, 256).
// ---------------------------------------------------------------------------
#define ROWB 80                              /* 64 data + 16 pad */
#define AH_OFF 0
#define AL_OFF (128*ROWB)                    /* 10240 */
#define BH_OFF (2*128*ROWB)                  /* 20480 */
#define BL_OFF (3*128*ROWB)                  /* 30720 */
#define STAGE_BYTES (4*128*ROWB)             /* 40960 */
#define BIAS_OFF (2*STAGE_BYTES)             /* 81920 */
#define GEMM_SMEM (BIAS_OFF + 512)

__global__ void __launch_bounds__(256, 2) gemm_hmma(const float* __restrict__ bias,
                                                    float* __restrict__ out)
{
    extern __shared__ char smem[];
    const uint32_t sb = smem_u32(smem);
    int tid  = threadIdx.x;
    int wid  = tid >> 5, lane = tid & 31;
    int n0   = blockIdx.x * 128;
    int m0   = blockIdx.y * 128;
    int wm   = (wid & 1) * 64;
    int wn   = (wid >> 1) * 32;

    if (tid < 128) ((float*)(smem + BIAS_OFF))[tid] = bias[n0 + tid];

    auto load_chunk = [&](int kt, int buf) {
        uint32_t st = sb + (uint32_t)buf * STAGE_BYTES;
        int koff = kt * 32;
#pragma unroll
        for (int i = 0; i < 2; i++) {
            int q = tid + i * 256;
            int r = q >> 2, c = q & 3;
            cp16(st + AH_OFF + r * ROWB + c * 16,
                 g_ah + (size_t)(m0 + r) * Kdim + koff + c * 8);
            cp16(st + AL_OFF + r * ROWB + c * 16,
                 g_al + (size_t)(m0 + r) * Kdim + koff + c * 8);
            cp16(st + BH_OFF + r * ROWB + c * 16,
                 g_bh + (size_t)(n0 + r) * Kdim + koff + c * 8);
            cp16(st + BL_OFF + r * ROWB + c * 16,
                 g_bl + (size_t)(n0 + r) * Kdim + koff + c * 8);
        }
        asm volatile("cp.async.commit_group;" ::: "memory");
    };

    const uint32_t a_off =
        (uint32_t)((wm + (lane & 7) + ((lane >> 3) & 1) * 8) * ROWB + ((lane >> 4) & 1) * 16);
    const uint32_t b_off =
        (uint32_t)((wn + (lane & 7) + ((lane >> 4) & 1) * 8) * ROWB + ((lane >> 3) & 1) * 16);

    float acc[4][4][4];
#pragma unroll
    for (int mi = 0; mi < 4; mi++)
#pragma unroll
        for (int ni = 0; ni < 4; ni++)
#pragma unroll
            for (int j = 0; j < 4; j++) acc[mi][ni][j] = 0.0f;

    load_chunk(0, 0);

    for (int kt = 0; kt < 32; kt++) {
        if (kt + 1 < 32) {
            load_chunk(kt + 1, (kt + 1) & 1);
            asm volatile("cp.async.wait_group 1;" ::: "memory");
        } else {
            asm volatile("cp.async.wait_group 0;" ::: "memory");
        }
        __syncthreads();

        uint32_t st = sb + (uint32_t)(kt & 1) * STAGE_BYTES;
#pragma unroll
        for (int s = 0; s < 2; s++) {
            uint32_t af[4][4], bh[4][2], blo[4][2];
#pragma unroll
            for (int mi = 0; mi < 4; mi++)
                ldsm4(af[mi], st + AH_OFF + a_off + mi * 16 * ROWB + s * 32);
#pragma unroll
            for (int j = 0; j < 2; j++) {
                uint32_t t4[4];
                ldsm4(t4, st + BH_OFF + b_off + j * 16 * ROWB + s * 32);
                bh[2 * j][0] = t4[0]; bh[2 * j][1] = t4[1];
                bh[2 * j + 1][0] = t4[2]; bh[2 * j + 1][1] = t4[3];
                ldsm4(t4, st + BL_OFF + b_off + j * 16 * ROWB + s * 32);
                blo[2 * j][0] = t4[0]; blo[2 * j][1] = t4[1];
                blo[2 * j + 1][0] = t4[2]; blo[2 * j + 1][1] = t4[3];
            }
#pragma unroll
            for (int mi = 0; mi < 4; mi++)
#pragma unroll
                for (int ni = 0; ni < 4; ni++) {
                    mma16816(acc[mi][ni], af[mi], bh[ni]);
                    mma16816(acc[mi][ni], af[mi], blo[ni]);
                }
#pragma unroll
            for (int mi = 0; mi < 4; mi++)
                ldsm4(af[mi], st + AL_OFF + a_off + mi * 16 * ROWB + s * 32);
#pragma unroll
            for (int mi = 0; mi < 4; mi++)
#pragma unroll
                for (int ni = 0; ni < 4; ni++)
                    mma16816(acc[mi][ni], af[mi], bh[ni]);
        }
        __syncthreads();
    }

    // ensure no cp.async is in flight before smem reuse
    asm volatile("cp.async.wait_all;" ::: "memory");
    __syncthreads();

    // epilogue: regs -> padded smem -> +bias -> coalesced float4 STG
    float* stg = (float*)smem;               // [128][132]
#pragma unroll
    for (int mi = 0; mi < 4; mi++)
#pragma unroll
        for (int ni = 0; ni < 4; ni++) {
            int r0 = wm + mi * 16 + (lane >> 2);
            int cc = wn + ni * 8 + (lane & 3) * 2;
            *(float2*)&stg[r0 * 132 + cc]       = make_float2(acc[mi][ni][0], acc[mi][ni][1]);
            *(float2*)&stg[(r0 + 8) * 132 + cc] = make_float2(acc[mi][ni][2], acc[mi][ni][3]);
        }
    __syncthreads();
    const float* bsm = (const float*)(smem + BIAS_OFF);
#pragma unroll
    for (int i = 0; i < 16; i++) {
        int f = tid + i * 256;
        int r = f >> 5, c4 = (f & 31) * 4;
        float4 v = *(const float4*)&stg[r * 132 + c4];
        v.x += bsm[c4]; v.y += bsm[c4 + 1]; v.z += bsm[c4 + 2]; v.w += bsm[c4 + 3];
        *(float4*)&out[(size_t)(m0 + r) * Cdim + n0 + c4] = v;
    }
}

// ---------------------------------------------------------------------------
extern "C" void kernel_launch(void* const* d_in, const int* in_sizes, int n_in,
                              void* d_out, int out_size)
{
    const float* x  = (const float*)d_in[0];
    const float* al = (const float*)d_in[1];
    const float* dl = (const float*)d_in[2];
    const float* bl = (const float*)d_in[3];
    const float* et = (const float*)d_in[4];
    const float* pw = (const float*)d_in[5];
    const float* pb = (const float*)d_in[6];
    float* out = (float*)d_out;

    cudaFuncSetAttribute(gemm_hmma, cudaFuncAttributeMaxDynamicSharedMemorySize, GEMM_SMEM);

    wconv_kernel<<<2048, 256>>>(pw);
    scan_kernel<<<dim3(2 * Bdim * (Cdim / 8)), 256>>>(x, al, dl, bl, et);
    gemm_hmma<<<dim3(Cdim / 128, Mdim / 128), 256, GEMM_SMEM>>>(pb, out);
}

// round 13
// speedup vs baseline: 4.2931x; 1.8438x over previous
// v12: fp16 single-term HMMA GEMM + clamp-aware scan
#include <cuda_runtime.h>
#include <cuda_fp16.h>
#include <cstdint>
#include <cstddef>

#define Bdim 8
#define Ndim 4096
#define Cdim 512
#define Hdim 4
#define Mdim (Bdim*Ndim)   /* 32768 */
#define Kdim (2*Cdim)      /* 1024  */

// A (scan output) [M][K] fp16; B (proj_w) [N][K] fp16
__device__ __align__(128) __half g_a[(size_t)Mdim * Kdim];
__device__ __align__(128) __half g_b[(size_t)Cdim * Kdim];

__device__ __forceinline__ float ex2f(float x) {
    float y;
    asm("ex2.approx.ftz.f32 %0, %1;" : "=f"(y) : "f"(x));
    return y;
}

__device__ __forceinline__ uint32_t smem_u32(const void* p) {
    uint32_t a;
    asm("{ .reg .u64 t; cvta.to.shared.u64 t, %1; cvt.u32.u64 %0, t; }" : "=r"(a) : "l"(p));
    return a;
}

__device__ __forceinline__ void cp16(uint32_t dst, const void* src) {
    asm volatile("cp.async.cg.shared.global [%0], [%1], 16;" :: "r"(dst), "l"(src));
}

__device__ __forceinline__ void ldsm4(uint32_t* r, uint32_t a) {
    asm volatile("ldmatrix.sync.aligned.m8n8.x4.shared.b16 {%0,%1,%2,%3}, [%4];"
        : "=r"(r[0]), "=r"(r[1]), "=r"(r[2]), "=r"(r[3]) : "r"(a));
}

__device__ __forceinline__ void mma16816(float* d, const uint32_t* a, const uint32_t* b) {
    asm volatile("mma.sync.aligned.m16n8k16.row.col.f32.f16.f16.f32 "
        "{%0,%1,%2,%3}, {%4,%5,%6,%7}, {%8,%9}, {%0,%1,%2,%3};"
        : "+f"(d[0]), "+f"(d[1]), "+f"(d[2]), "+f"(d[3])
        : "r"(a[0]), "r"(a[1]), "r"(a[2]), "r"(a[3]), "r"(b[0]), "r"(b[1]));
}

// ---------------------------------------------------------------------------
// W convert: g_b[n][k] = fp16(proj_w[n][k])
// ---------------------------------------------------------------------------
__global__ void wconv_kernel(const float* __restrict__ W)
{
    int i = blockIdx.x * 256 + threadIdx.x;   // 2048 x 256
    g_b[i] = __float2half_rn(W[i]);
}

// ---------------------------------------------------------------------------
// Clipped EMA scan (fwd + bwd) -> fp16 in [M][K]
// grid = 2*B*(C/8) = 1024 blocks, 256 threads (8 warps = 8 channels)
// 128-step tiles; warp-uniform 3-way clamp branch (clamped tiles: 0 MUFU)
// ---------------------------------------------------------------------------
#define XS_STRIDE 140
#define YS_STRIDE 136

__global__ __launch_bounds__(256) void scan_kernel(
    const float* __restrict__ x,
    const float* __restrict__ al, const float* __restrict__ dl,
    const float* __restrict__ bl, const float* __restrict__ eta)
{
    const int CG = Cdim / 8;
    int blk = blockIdx.x;
    int cg  = blk % CG;
    int b   = (blk / CG) % Bdim;
    int dir = blk / (CG * Bdim);
    int c0  = cg * 8;

    __shared__ float xs2[8 * XS_STRIDE];   // [c][t]
    __shared__ float ys2[8 * YS_STRIDE];   // [c][t]
    __shared__ float sA[8][4], sLr[8][4], sEt[8][4];

    int tid = threadIdx.x;
    if (tid < 32) {
        int cc = tid >> 2, hh = tid & 3;
        int idx = (c0 + cc) * Hdim + hh;
        float a  = 1.0f / (1.0f + expf(-al[idx]));
        float dd = 1.0f / (1.0f + expf(-dl[idx]));
        float be = 1.0f / (1.0f + expf(-bl[idx]));
        float r  = 1.0f - a * dd;
        r = fminf(fmaxf(r, 1e-4f), 1.0f - 1e-4f);
        sA[cc][hh]  = a * be;
        sLr[cc][hh] = log2f(r);
        sEt[cc][hh] = eta[idx];
    }
    __syncthreads();

    int w = tid >> 5, lane = tid & 31;
    const float QC = 1.1420074e+26f;   // exp(60)  (fp32 of e^60)
    const float PC = 8.7565108e-27f;   // exp(-60)
    float Ah[4], Lr[4], Et[4], carry[4], AhQ[4], EtP[4];
#pragma unroll
    for (int hh = 0; hh < 4; hh++) {
        Ah[hh] = sA[w][hh]; Lr[hh] = sLr[w][hh]; Et[hh] = sEt[w][hh];
        carry[hh] = 0.0f;
        AhQ[hh] = Ah[hh] * QC;
        EtP[hh] = Et[hh] * PC;
    }

    const float CLP = 86.56170245333781f;   // 60 * log2(e)
    int ldt = tid >> 1, ldh = tid & 1;      // loader lanes

    for (int t0 = 0; t0 < Ndim; t0 += 128) {
        // load x tile [128 t][8 c] -> xs2 [c][t] transposed
        {
            int n_ld = dir ? (Ndim - 1 - (t0 + ldt)) : (t0 + ldt);
            float4 v = *(const float4*)&x[((size_t)b * Ndim + n_ld) * Cdim + c0 + ldh * 4];
            xs2[(ldh * 4 + 0) * XS_STRIDE + ldt] = v.x;
            xs2[(ldh * 4 + 1) * XS_STRIDE + ldt] = v.y;
            xs2[(ldh * 4 + 2) * XS_STRIDE + ldt] = v.z;
            xs2[(ldh * 4 + 3) * XS_STRIDE + ldt] = v.w;
        }
        __syncthreads();

        float4 xq = *(const float4*)&xs2[w * XS_STRIDE + lane * 4];
        float xv[4] = {xq.x, xq.y, xq.z, xq.w};
        float yv[4] = {0.0f, 0.0f, 0.0f, 0.0f};
        float s0f = (float)(t0 + lane * 4);
        float tf0 = (float)t0;

#pragma unroll
        for (int hh = 0; hh < 4; hh++) {
            float lr = Lr[hh];
            float z[4], mu[4];
            if (lr * tf0 <= -CLP) {
                // fully clamped tile: p=PC, q=QC constants, zero MUFU
                float aq = AhQ[hh], ep = EtP[hh];
#pragma unroll
                for (int j = 0; j < 4; j++) { z[j] = aq * xv[j]; mu[j] = ep; }
            } else if (lr * (tf0 + 127.0f) >= -CLP) {
                // fully unclamped: 2 MUFU for base, ratios by multiply
                float e0  = lr * s0f;
                float p0  = ex2f(e0), q0 = ex2f(-e0);
                float rp1 = ex2f(lr), rq1 = ex2f(-lr);
                float rp2 = rp1 * rp1, rq2 = rq1 * rq1;
                float rp3 = rp2 * rp1, rq3 = rq2 * rq1;
                float aq0 = Ah[hh] * q0, ep0 = Et[hh] * p0;
                z[0] = aq0 * xv[0];        mu[0] = ep0;
                z[1] = aq0 * rq1 * xv[1];  mu[1] = ep0 * rp1;
                z[2] = aq0 * rq2 * xv[2];  mu[2] = ep0 * rp2;
                z[3] = aq0 * rq3 * xv[3];  mu[3] = ep0 * rp3;
            } else {
                // crossing tile (<=1 per channel): per-element exact path
#pragma unroll
                for (int j = 0; j < 4; j++) {
                    float e = fmaxf(lr * (s0f + (float)j), -CLP);
                    float p = ex2f(e);
                    z[j]  = Ah[hh] * xv[j] * ex2f(-e);
                    mu[j] = Et[hh] * p;
                }
            }
            z[1] += z[0]; z[2] += z[1]; z[3] += z[2];   // local inclusive
            float tot = z[3];
            float ss = tot;
#pragma unroll
            for (int o = 1; o < 32; o <<= 1) {
                float v = __shfl_up_sync(0xffffffffu, ss, o);
                if (lane >= o) ss += v;
            }
            float blkTot = __shfl_sync(0xffffffffu, ss, 31);
            float pre = ss - tot + carry[hh];
#pragma unroll
            for (int j = 0; j < 4; j++)
                yv[j] = fmaf(mu[j], pre + z[j], yv[j]);
            carry[hh] += blkTot;
        }

        *(float4*)&ys2[w * YS_STRIDE + lane * 4] = make_float4(yv[0], yv[1], yv[2], yv[3]);
        __syncthreads();

        // writers: 128 threads, each packs 8 channels for one timestep (fp16)
        if (tid < 128) {
            int n_st = dir ? (Ndim - 1 - (t0 + tid)) : (t0 + tid);
            size_t m = (size_t)b * Ndim + n_st;
            uint4 u;
            unsigned* up = (unsigned*)&u;
#pragma unroll
            for (int j = 0; j < 4; j++) {
                __half2 pk = __floats2half2_rn(ys2[(2 * j) * YS_STRIDE + tid],
                                               ys2[(2 * j + 1) * YS_STRIDE + tid]);
                up[j] = *(unsigned*)&pk;
            }
            *(uint4*)(g_a + m * Kdim + dir * Cdim + c0) = u;
        }
        __syncthreads();
    }
}

// ---------------------------------------------------------------------------
// fp16 HMMA GEMM: out[m][n] = bias[n] + sum_k z[m][k]W[n][k]
// CTA tile 128x128, K-chunk 64, 3-stage cp.async, 256 threads (8 warps,
// warp tile 64x32), 2 CTAs/SM. grid (4, 256).
// ---------------------------------------------------------------------------
#define ROWB2 144                            /* 128 data + 16 pad */
#define A_OFF 0
#define B_OFF (128*ROWB2)                    /* 18432 */
#define STG2 (2*128*ROWB2)                   /* 36864 */
#define BIAS2 (3*STG2)                       /* 110592 */
#define GSM (BIAS2 + 512)

__global__ void __launch_bounds__(256, 2) gemm_hmma(const float* __restrict__ bias,
                                                    float* __restrict__ out)
{
    extern __shared__ char smem[];
    const uint32_t sb = smem_u32(smem);
    int tid  = threadIdx.x;
    int wid  = tid >> 5, lane = tid & 31;
    int n0   = blockIdx.x * 128;
    int m0   = blockIdx.y * 128;
    int wm   = (wid & 1) * 64;
    int wn   = (wid >> 1) * 32;

    if (tid < 128) ((float*)(smem + BIAS2))[tid] = bias[n0 + tid];

    auto load_chunk = [&](int kt, int buf) {
        uint32_t st = sb + (uint32_t)buf * STG2;
        int koff = kt * 64;
#pragma unroll
        for (int i = 0; i < 4; i++) {
            int q = tid + i * 256;           // 0..1023
            int r = q >> 3, c = q & 7;
            cp16(st + A_OFF + r * ROWB2 + c * 16,
                 g_a + (size_t)(m0 + r) * Kdim + koff + c * 8);
            cp16(st + B_OFF + r * ROWB2 + c * 16,
                 g_b + (size_t)(n0 + r) * Kdim + koff + c * 8);
        }
        asm volatile("cp.async.commit_group;" ::: "memory");
    };

    const uint32_t a_off =
        (uint32_t)((wm + (lane & 7) + ((lane >> 3) & 1) * 8) * ROWB2 + ((lane >> 4) & 1) * 16);
    const uint32_t b_off =
        (uint32_t)((wn + (lane & 7) + ((lane >> 4) & 1) * 8) * ROWB2 + ((lane >> 3) & 1) * 16);

    float acc[4][4][4];
#pragma unroll
    for (int mi = 0; mi < 4; mi++)
#pragma unroll
        for (int ni = 0; ni < 4; ni++)
#pragma unroll
            for (int j = 0; j < 4; j++) acc[mi][ni][j] = 0.0f;

    load_chunk(0, 0);
    load_chunk(1, 1);

    for (int kt = 0; kt < 16; kt++) {
        if (kt + 2 < 16) load_chunk(kt + 2, (kt + 2) % 3);
        if (kt < 14)       asm volatile("cp.async.wait_group 2;" ::: "memory");
        else if (kt == 14) asm volatile("cp.async.wait_group 1;" ::: "memory");
        else               asm volatile("cp.async.wait_group 0;" ::: "memory");
        __syncthreads();

        uint32_t st = sb + (uint32_t)(kt % 3) * STG2;
#pragma unroll
        for (int s = 0; s < 4; s++) {
            uint32_t af[4][4], bf2[4][2];
#pragma unroll
            for (int mi = 0; mi < 4; mi++)
                ldsm4(af[mi], st + A_OFF + a_off + mi * 16 * ROWB2 + s * 32);
#pragma unroll
            for (int j = 0; j < 2; j++) {
                uint32_t t4[4];
                ldsm4(t4, st + B_OFF + b_off + j * 16 * ROWB2 + s * 32);
                bf2[2 * j][0] = t4[0]; bf2[2 * j][1] = t4[1];
                bf2[2 * j + 1][0] = t4[2]; bf2[2 * j + 1][1] = t4[3];
            }
#pragma unroll
            for (int mi = 0; mi < 4; mi++)
#pragma unroll
                for (int ni = 0; ni < 4; ni++)
                    mma16816(acc[mi][ni], af[mi], bf2[ni]);
        }
        __syncthreads();
    }

    // ensure no cp.async in flight before smem reuse
    asm volatile("cp.async.wait_all;" ::: "memory");
    __syncthreads();

    // epilogue: regs -> padded smem -> +bias -> coalesced float4 STG
    float* stg = (float*)smem;               // [128][132]
#pragma unroll
    for (int mi = 0; mi < 4; mi++)
#pragma unroll
        for (int ni = 0; ni < 4; ni++) {
            int r0 = wm + mi * 16 + (lane >> 2);
            int cc = wn + ni * 8 + (lane & 3) * 2;
            *(float2*)&stg[r0 * 132 + cc]       = make_float2(acc[mi][ni][0], acc[mi][ni][1]);
            *(float2*)&stg[(r0 + 8) * 132 + cc] = make_float2(acc[mi][ni][2], acc[mi][ni][3]);
        }
    __syncthreads();
    const float* bsm = (const float*)(smem + BIAS2);
#pragma unroll
    for (int i = 0; i < 16; i++) {
        int f = tid + i * 256;
        int r = f >> 5, c4 = (f & 31) * 4;
        float4 v = *(const float4*)&stg[r * 132 + c4];
        v.x += bsm[c4]; v.y += bsm[c4 + 1]; v.z += bsm[c4 + 2]; v.w += bsm[c4 + 3];
        *(float4*)&out[(size_t)(m0 + r) * Cdim + n0 + c4] = v;
    }
}

// ---------------------------------------------------------------------------
extern "C" void kernel_launch(void* const* d_in, const int* in_sizes, int n_in,
                              void* d_out, int out_size)
{
    const float* x  = (const float*)d_in[0];
    const float* al = (const float*)d_in[1];
    const float* dl = (const float*)d_in[2];
    const float* bl = (const float*)d_in[3];
    const float* et = (const float*)d_in[4];
    const float* pw = (const float*)d_in[5];
    const float* pb = (const float*)d_in[6];
    float* out = (float*)d_out;

    cudaFuncSetAttribute(gemm_hmma, cudaFuncAttributeMaxDynamicSharedMemorySize, GSM);

    wconv_kernel<<<2048, 256>>>(pw);
    scan_kernel<<<dim3(2 * Bdim * (Cdim / 8)), 256>>>(x, al, dl, bl, et);
    gemm_hmma<<<dim3(Cdim / 128, Mdim / 128), 256, GSM>>>(pb, out);
}